// round 16
// baseline (speedup 1.0000x reference)
#include <cuda_runtime.h>
#include <cuda_bf16.h>
#include <cstdint>

#define NN 100000
#define EE 1200000
#define HH 64
#define EDD 16
#define LL 3
#define GG 1000
#define NB_SCAN ((NN + 1023) / 1024)

// ---------------- device scratch ----------------
__device__ __align__(256) float g_h[NN * HH];
__device__ __align__(256) float g_S[NN * HH];
__device__ __align__(256) float g_tmp[NN * HH];
__device__ __align__(256) float g_aggea[NN * EDD];
__device__ __align__(256) float g_cnt[GG];
__device__ __align__(256) float g_sum[GG * HH];
__device__ __align__(256) float g_sumsq[GG * HH];
__device__ __align__(256) float g_mean[GG * HH];
__device__ __align__(256) float g_istd[GG * HH];
__device__ __align__(256) float g_A[LL * HH * HH];
__device__ __align__(256) float g_B[LL * HH * HH];
__device__ __align__(256) float g_C[LL * EDD * HH];
__device__ __align__(256) float g_c1[LL * HH];
__device__ __align__(256) float g_c2[LL * HH];
__device__ __align__(256) int g_degi[NN];
__device__ __align__(256) int g_rowoff[NN];
__device__ __align__(256) int g_cursor[NN];
__device__ __align__(256) int g_csrsrc[EE];
__device__ __align__(256) int g_bsum[NB_SCAN];

// ---------------- helpers ----------------
__device__ __forceinline__ uint64_t pack2(float lo, float hi) {
    uint64_t r; asm("mov.b64 %0, {%1,%2};" : "=l"(r) : "f"(lo), "f"(hi)); return r;
}
__device__ __forceinline__ void fma2(uint64_t& d, uint64_t a, uint64_t b) {
    asm("fma.rn.f32x2 %0, %1, %2, %0;" : "+l"(d) : "l"(a), "l"(b));
}
__device__ __forceinline__ float fold2(uint64_t a) {
    float lo, hi; asm("mov.b64 {%0,%1}, %2;" : "=f"(lo), "=f"(hi) : "l"(a)); return lo + hi;
}
__device__ __forceinline__ void red4(float* p, float4 v) {
    asm volatile("red.global.add.v4.f32 [%0], {%1,%2,%3,%4};"
                 :: "l"(p), "f"(v.x), "f"(v.y), "f"(v.z), "f"(v.w) : "memory");
}

// ---------------- once-per-call precompute ----------------
__global__ void k_zero_init() {
    const int o1 = NN * EDD, o2 = o1 + NN, o3 = o2 + GG, o4 = o3 + GG * HH, o5 = o4 + GG * HH;
    for (int i = blockIdx.x * blockDim.x + threadIdx.x; i < o5; i += gridDim.x * blockDim.x) {
        if (i < o1)      g_aggea[i] = 0.f;
        else if (i < o2) g_degi[i - o1] = 0;
        else if (i < o3) g_cnt[i - o2] = 0.f;
        else if (i < o4) g_sum[i - o3] = 0.f;
        else             g_sumsq[i - o4] = 0.f;
    }
}

// edge aggregation: 4 threads per edge (independent red4 per thread) + per-graph counts
__global__ void k_edge_pre(const int* __restrict__ ei, const float* __restrict__ ea,
                           const int* __restrict__ batch) {
    int t = blockIdx.x * 256 + threadIdx.x;
    if (t < EE * 4) {
        int e = t >> 2, q = t & 3;
        int d = __ldg(ei + EE + e);
        float4 v = __ldg((const float4*)(ea + (size_t)e * EDD) + q);
        red4(&g_aggea[(size_t)d * EDD + q * 4], v);
        if (q == 0) atomicAdd(&g_degi[d], 1);
    } else if (t < EE * 4 + NN) {
        int n = t - EE * 4;
        atomicAdd(&g_cnt[__ldg(batch + n)], 1.0f);
    }
}

__global__ void k_scan1() {
    __shared__ int warpsum[32];
    int tid = threadIdx.x, lane = tid & 31, w = tid >> 5;
    int i = blockIdx.x * 1024 + tid;
    int v = (i < NN) ? g_degi[i] : 0;
    int s = v;
#pragma unroll
    for (int o = 1; o < 32; o <<= 1) { int t = __shfl_up_sync(~0u, s, o); if (lane >= o) s += t; }
    if (lane == 31) warpsum[w] = s;
    __syncthreads();
    if (w == 0) {
        int ws = warpsum[lane];
#pragma unroll
        for (int o = 1; o < 32; o <<= 1) { int t = __shfl_up_sync(~0u, ws, o); if (lane >= o) ws += t; }
        warpsum[lane] = ws;
    }
    __syncthreads();
    int excl = s - v + (w ? warpsum[w - 1] : 0);
    if (i < NN) g_rowoff[i] = excl;
    if (tid == 1023) g_bsum[blockIdx.x] = excl + v;
}

__global__ void k_scan2() {
    __shared__ int warpsum[4];
    int tid = threadIdx.x, lane = tid & 31, w = tid >> 5;
    int v = (tid < NB_SCAN) ? g_bsum[tid] : 0;
    int s = v;
#pragma unroll
    for (int o = 1; o < 32; o <<= 1) { int t = __shfl_up_sync(~0u, s, o); if (lane >= o) s += t; }
    if (lane == 31) warpsum[w] = s;
    __syncthreads();
    int add = 0;
    for (int ww = 0; ww < w; ww++) add += warpsum[ww];
    if (tid < NB_SCAN) g_bsum[tid] = s - v + add;
}

__global__ void k_scan3() {
    int i = blockIdx.x * blockDim.x + threadIdx.x;
    if (i >= NN) return;
    int val = g_rowoff[i] + g_bsum[i >> 10];
    g_rowoff[i] = val;
    g_cursor[i] = val;
}

__global__ void k_place(const int* __restrict__ ei) {
    int e = blockIdx.x * 256 + threadIdx.x;
    if (e >= EE) return;
    int d = __ldg(ei + EE + e);
    int s = __ldg(ei + e);
    int pos = atomicAdd(&g_cursor[d], 1);
    g_csrsrc[pos] = s;
}

// fused weights for ALL layers in one launch
__global__ void k_pre(const float* __restrict__ nodeW, const float* __restrict__ edgeW,
                      const float* __restrict__ nodeb, const float* __restrict__ edgeb,
                      const float* __restrict__ m1W,   const float* __restrict__ m1b) {
    int j = threadIdx.x;
    int l = blockIdx.x / 81;
    int kb = blockIdx.x % 81;
    const float* nW = nodeW + l * 4096;
    const float* eW = edgeW + l * 1024;
    const float* nb = nodeb + l * 64;
    const float* eb = edgeb + l * 64;
    const float* w1 = m1W + l * 8192;
    const float* b1 = m1b + l * 64;
    if (kb < 64) {
        float a = 0.f, b = 0.f;
        for (int m = 0; m < 64; m++) {
            float wn = __ldg(nW + kb * 64 + m);
            a = fmaf(wn, __ldg(w1 + m * 64 + j), a);
            b = fmaf(wn, __ldg(w1 + (64 + m) * 64 + j), b);
        }
        g_A[l * 4096 + kb * 64 + j] = a;
        g_B[l * 4096 + kb * 64 + j] = b;
    } else if (kb < 80) {
        int k = kb - 64;
        float c = 0.f;
        for (int m = 0; m < 64; m++)
            c = fmaf(__ldg(eW + k * 64 + m), __ldg(w1 + (64 + m) * 64 + j), c);
        g_C[l * 1024 + k * 64 + j] = c;
    } else {
        float s1 = __ldg(b1 + j), s2 = 0.f;
        for (int m = 0; m < 64; m++) {
            s1 = fmaf(__ldg(nb + m), __ldg(w1 + m * 64 + j), s1);
            s2 = fmaf(__ldg(nb + m) + __ldg(eb + m), __ldg(w1 + (64 + m) * 64 + j), s2);
        }
        g_c1[l * 64 + j] = s1;
        g_c2[l * 64 + j] = s2;
    }
}

// ---------------- encoder: h = x @ enc_W + enc_b  (f32x2) ----------------
__global__ void __launch_bounds__(256, 2)
k_encoder(const float* __restrict__ X, const float* __restrict__ W, const float* __restrict__ Bv) {
    const int j = threadIdx.x, y = threadIdx.y;
    uint64_t w2[32];
#pragma unroll
    for (int p = 0; p < 32; p++)
        w2[p] = pack2(__ldg(W + (2 * p) * 64 + j), __ldg(W + (2 * p + 1) * 64 + j));
    const float bj = __ldg(Bv + j);
    __shared__ __align__(16) float xs[2][4][64];
    const int nT = NN / 4;
    int per = (nT + gridDim.x - 1) / gridDim.x;
    int t0 = blockIdx.x * per, t1 = min(nT, t0 + per);
    if (t0 >= t1) return;
    float pf = __ldg(X + (size_t)(t0 * 4 + y) * 64 + j);
    for (int tile = t0; tile < t1; ++tile) {
        int cur = tile & 1;
        xs[cur][y][j] = pf;
        __syncthreads();
        if (tile + 1 < t1) pf = __ldg(X + (size_t)((tile + 1) * 4 + y) * 64 + j);
        const uint64_t* xr = (const uint64_t*)xs[cur][y];
        uint64_t a0 = 0, a1 = 0, a2 = 0, a3 = 0;
#pragma unroll
        for (int p = 0; p < 32; p += 4) {
            fma2(a0, xr[p],     w2[p]);
            fma2(a1, xr[p + 1], w2[p + 1]);
            fma2(a2, xr[p + 2], w2[p + 2]);
            fma2(a3, xr[p + 3], w2[p + 3]);
        }
        g_h[(size_t)(tile * 4 + y) * 64 + j] = (fold2(a0) + fold2(a1)) + (fold2(a2) + fold2(a3)) + bj;
    }
}

// ---------------- gather (float4, unroll 8, occ 6 — champion config) ----------------
__global__ void __launch_bounds__(256, 6)
k_gather4() {
    const int j = threadIdx.x;
    const int y = threadIdx.y;
    int r = blockIdx.x * 16 + y;
    if (r >= NN) return;
    int p = __ldg(g_rowoff + r);
    const int p1 = (r + 1 < NN) ? __ldg(g_rowoff + r + 1) : EE;
    float4 a0 = make_float4(0.f, 0.f, 0.f, 0.f);
    float4 a1 = make_float4(0.f, 0.f, 0.f, 0.f);
    for (; p + 7 < p1; p += 8) {
        int s0 = __ldg(g_csrsrc + p);
        int s1 = __ldg(g_csrsrc + p + 1);
        int s2 = __ldg(g_csrsrc + p + 2);
        int s3 = __ldg(g_csrsrc + p + 3);
        int s4 = __ldg(g_csrsrc + p + 4);
        int s5 = __ldg(g_csrsrc + p + 5);
        int s6 = __ldg(g_csrsrc + p + 6);
        int s7 = __ldg(g_csrsrc + p + 7);
        float4 v0 = __ldg((const float4*)(g_h + (size_t)s0 * 64) + j);
        float4 v1 = __ldg((const float4*)(g_h + (size_t)s1 * 64) + j);
        float4 v2 = __ldg((const float4*)(g_h + (size_t)s2 * 64) + j);
        float4 v3 = __ldg((const float4*)(g_h + (size_t)s3 * 64) + j);
        float4 v4 = __ldg((const float4*)(g_h + (size_t)s4 * 64) + j);
        float4 v5 = __ldg((const float4*)(g_h + (size_t)s5 * 64) + j);
        float4 v6 = __ldg((const float4*)(g_h + (size_t)s6 * 64) + j);
        float4 v7 = __ldg((const float4*)(g_h + (size_t)s7 * 64) + j);
        a0.x += v0.x; a0.y += v0.y; a0.z += v0.z; a0.w += v0.w;
        a1.x += v1.x; a1.y += v1.y; a1.z += v1.z; a1.w += v1.w;
        a0.x += v2.x; a0.y += v2.y; a0.z += v2.z; a0.w += v2.w;
        a1.x += v3.x; a1.y += v3.y; a1.z += v3.z; a1.w += v3.w;
        a0.x += v4.x; a0.y += v4.y; a0.z += v4.z; a0.w += v4.w;
        a1.x += v5.x; a1.y += v5.y; a1.z += v5.z; a1.w += v5.w;
        a0.x += v6.x; a0.y += v6.y; a0.z += v6.z; a0.w += v6.w;
        a1.x += v7.x; a1.y += v7.y; a1.z += v7.z; a1.w += v7.w;
    }
    for (; p < p1; p++) {
        int s = __ldg(g_csrsrc + p);
        float4 v = __ldg((const float4*)(g_h + (size_t)s * 64) + j);
        a0.x += v.x; a0.y += v.y; a0.z += v.z; a0.w += v.w;
    }
    float4 o;
    o.x = a0.x + a1.x; o.y = a0.y + a1.y; o.z = a0.z + a1.z; o.w = a0.w + a1.w;
    ((float4*)(g_S + (size_t)r * 64))[j] = o;
}

// ---------------- merged fuse: 16-row tiles, 4 rows/thread, rows-outer loops ----------------
// Phase A scalar FMA (LDS.128 operands), Phase B FFMA2. Persistent 148 blocks, occ 1.
__global__ void __launch_bounds__(256, 1)
k_fuse(int l, const float* __restrict__ W2, const float* __restrict__ b2v,
       const int* __restrict__ batch) {
    const int j = threadIdx.x, y = threadIdx.y;   // thread owns rows y, y+4, y+8, y+12
    const float* gA = g_A + l * 4096;
    const float* gB = g_B + l * 4096;
    const float* gC = g_C + l * 1024;
    float wa[64], wb[64];
#pragma unroll
    for (int k = 0; k < 64; k++) { wa[k] = gA[k * 64 + j]; wb[k] = gB[k * 64 + j]; }
    uint64_t w2[32];
#pragma unroll
    for (int p = 0; p < 32; p++)
        w2[p] = pack2(__ldg(W2 + (2 * p) * 64 + j), __ldg(W2 + (2 * p + 1) * 64 + j));
    const float b1 = g_c1[l * 64 + j], b2 = g_c2[l * 64 + j];
    const float bj2 = __ldg(b2v + j);

    __shared__ __align__(16) float hs[2][16][64], Ss[2][16][64], eas[2][16][16];
    __shared__ float degs[2][16];
    __shared__ float Csh[16][64];
    __shared__ __align__(16) float Tsh[16][64];
    {
        int tid = y * 64 + j;
        for (int i = tid; i < 16 * 64; i += 256) Csh[i >> 6][i & 63] = gC[i];
    }
    const int nT = NN / 16;   // 6250 exact
    int per = (nT + gridDim.x - 1) / gridDim.x;
    int t0 = blockIdx.x * per, t1 = min(nT, t0 + per);
    if (t0 >= t1) return;

    float cs[4] = {0.f, 0.f, 0.f, 0.f}, cq[4] = {0.f, 0.f, 0.f, 0.f};
    int cg[4] = {-1, -1, -1, -1};

    float ph[4], pS[4], pea[4] = {0.f, 0.f, 0.f, 0.f}, pd[4] = {0.f, 0.f, 0.f, 0.f};
#pragma unroll
    for (int i = 0; i < 4; i++) {
        size_t r = (size_t)(t0 * 16 + y + 4 * i);
        ph[i] = __ldg(g_h + r * 64 + j);
        pS[i] = __ldg(g_S + r * 64 + j);
        if (j < 16) pea[i] = __ldg(g_aggea + r * 16 + j);
        if (j == 0) pd[i] = (float)__ldg(g_degi + (int)r);
    }
    for (int tile = t0; tile < t1; ++tile) {
        int cur = tile & 1;
#pragma unroll
        for (int i = 0; i < 4; i++) {
            int row = y + 4 * i;
            hs[cur][row][j] = ph[i];
            Ss[cur][row][j] = pS[i];
            if (j < 16) eas[cur][row][j] = pea[i];
            if (j == 0) degs[cur][row] = pd[i];
        }
        __syncthreads();
        if (tile + 1 < t1) {
#pragma unroll
            for (int i = 0; i < 4; i++) {
                size_t r = (size_t)((tile + 1) * 16 + y + 4 * i);
                ph[i] = __ldg(g_h + r * 64 + j);
                pS[i] = __ldg(g_S + r * 64 + j);
                if (j < 16) pea[i] = __ldg(g_aggea + r * 16 + j);
                if (j == 0) pd[i] = (float)__ldg(g_degi + (int)r);
            }
        }
        // ---- Phase A: rows y+4i, scalar FMA, 2+2 chains per row ----
#pragma unroll
        for (int i = 0; i < 4; i++) {
            int row = y + 4 * i;
            const float4* h4 = (const float4*)hs[cur][row];
            const float4* S4 = (const float4*)Ss[cur][row];
            float u0 = 0.f, u1 = 0.f, v0 = 0.f, v1 = 0.f;
#pragma unroll
            for (int q = 0; q < 16; q++) {
                float4 ha = h4[q];
                float4 sa = S4[q];
                u0 = fmaf(ha.x, wa[4 * q],     u0);
                u1 = fmaf(ha.y, wa[4 * q + 1], u1);
                u0 = fmaf(ha.z, wa[4 * q + 2], u0);
                u1 = fmaf(ha.w, wa[4 * q + 3], u1);
                v0 = fmaf(sa.x, wb[4 * q],     v0);
                v1 = fmaf(sa.y, wb[4 * q + 1], v1);
                v0 = fmaf(sa.z, wb[4 * q + 2], v0);
                v1 = fmaf(sa.w, wb[4 * q + 3], v1);
            }
            const float4* e4 = (const float4*)eas[cur][row];
#pragma unroll
            for (int q = 0; q < 4; q++) {
                float4 ca = e4[q];
                u0 = fmaf(ca.x, Csh[4 * q][j],     u0);
                u1 = fmaf(ca.y, Csh[4 * q + 1][j], u1);
                u0 = fmaf(ca.z, Csh[4 * q + 2][j], u0);
                u1 = fmaf(ca.w, Csh[4 * q + 3][j], u1);
            }
            float val = (u0 + u1) + (v0 + v1) + b1 + degs[cur][row] * b2;
            Tsh[row][j] = fmaxf(val, 0.f);
        }
        __syncthreads();
        // ---- Phase B: rows y+4i, tmp = Tsh @ W2 + b2 (FFMA2), plus stats ----
#pragma unroll
        for (int i = 0; i < 4; i++) {
            int row = y + 4 * i;
            const ulonglong2* tr = (const ulonglong2*)Tsh[row];
            uint64_t a0 = 0, a1 = 0, a2 = 0, a3 = 0;
#pragma unroll
            for (int q = 0; q < 16; q += 2) {
                ulonglong2 ta = tr[q];
                ulonglong2 ta2 = tr[q + 1];
                fma2(a0, ta.x,  w2[2 * q]);
                fma2(a1, ta.y,  w2[2 * q + 1]);
                fma2(a2, ta2.x, w2[2 * q + 2]);
                fma2(a3, ta2.y, w2[2 * q + 3]);
            }
            int r = tile * 16 + row;
            float v = (fold2(a0) + fold2(a1)) + (fold2(a2) + fold2(a3)) + bj2;
            g_tmp[(size_t)r * 64 + j] = v;
            int g = __ldg(batch + r);
            if (g != cg[i]) {
                if (cg[i] >= 0) {
                    atomicAdd(&g_sum[cg[i] * 64 + j], cs[i]);
                    atomicAdd(&g_sumsq[cg[i] * 64 + j], cq[i]);
                }
                cg[i] = g; cs[i] = 0.f; cq[i] = 0.f;
            }
            cs[i] += v; cq[i] += v * v;
        }
    }
#pragma unroll
    for (int i = 0; i < 4; i++) {
        if (cg[i] >= 0) {
            atomicAdd(&g_sum[cg[i] * 64 + j], cs[i]);
            atomicAdd(&g_sumsq[cg[i] * 64 + j], cq[i]);
        }
    }
}

// compute mean/istd, then zero stats for next layer
__global__ void k_fin() {
    int i = blockIdx.x * blockDim.x + threadIdx.x;
    if (i >= GG * HH) return;
    int g = i >> 6;
    float c = fmaxf(g_cnt[g], 1.0f);
    float m = g_sum[i] / c;
    float v = g_sumsq[i] / c - m * m;
    g_mean[i] = m;
    g_istd[i] = rsqrtf(v + 1e-5f);
    g_sum[i] = 0.f;
    g_sumsq[i] = 0.f;
}

__global__ void k_norm(const int* __restrict__ batch, const float* __restrict__ nw,
                       const float* __restrict__ nb, float* __restrict__ out) {
    int i = blockIdx.x * blockDim.x + threadIdx.x;
    if (i >= NN * 16) return;
    int n = i >> 4, q = i & 15;
    int g = __ldg(batch + n);
    float4 t  = *((const float4*)g_tmp + i);
    float4 m  = *((const float4*)g_mean + g * 16 + q);
    float4 is = *((const float4*)g_istd + g * 16 + q);
    float4 w  = __ldg((const float4*)nw + q);
    float4 b  = __ldg((const float4*)nb + q);
    float4 r  = *((const float4*)g_h + i);
    float4 o;
    o.x = fmaxf(fmaf(w.x, (t.x - m.x) * is.x, b.x), 0.f) + r.x;
    o.y = fmaxf(fmaf(w.y, (t.y - m.y) * is.y, b.y), 0.f) + r.y;
    o.z = fmaxf(fmaf(w.z, (t.z - m.z) * is.z, b.z), 0.f) + r.z;
    o.w = fmaxf(fmaf(w.w, (t.w - m.w) * is.w, b.w), 0.f) + r.w;
    float4* dst = out ? (float4*)out : (float4*)g_h;
    dst[i] = o;
}

// ---------------- launch ----------------
extern "C" void kernel_launch(void* const* d_in, const int* in_sizes, int n_in,
                              void* d_out, int out_size) {
    const float* x     = (const float*)d_in[0];
    const int*   ei    = (const int*)  d_in[1];
    const float* ea    = (const float*)d_in[2];
    const int*   batch = (const int*)  d_in[3];
    const float* encW  = (const float*)d_in[4];
    const float* encb  = (const float*)d_in[5];
    const float* nodeW = (const float*)d_in[6];
    const float* nodeb = (const float*)d_in[7];
    const float* edgeW = (const float*)d_in[8];
    const float* edgeb = (const float*)d_in[9];
    const float* m1W   = (const float*)d_in[10];
    const float* m1b   = (const float*)d_in[11];
    const float* m2W   = (const float*)d_in[12];
    const float* m2b   = (const float*)d_in[13];
    const float* nw    = (const float*)d_in[14];
    const float* nb    = (const float*)d_in[15];

    dim3 blk(64, 4);
    dim3 gblk(16, 16);

    static cudaStream_t s2 = nullptr;
    static cudaEvent_t evFork = nullptr, evJoin = nullptr;
    if (!s2) {
        cudaStreamCreateWithFlags(&s2, cudaStreamNonBlocking);
        cudaEventCreateWithFlags(&evFork, cudaEventDisableTiming);
        cudaEventCreateWithFlags(&evJoin, cudaEventDisableTiming);
    }

    // fork: side stream runs k_pre + encoder concurrently with the CSR build
    cudaEventRecord(evFork, 0);
    cudaStreamWaitEvent(s2, evFork, 0);
    k_pre<<<LL * 81, 64, 0, s2>>>(nodeW, edgeW, nodeb, edgeb, m1W, m1b);
    k_encoder<<<296, blk, 0, s2>>>(x, encW, encb);
    cudaEventRecord(evJoin, s2);

    // main stream: CSR build chain
    k_zero_init<<<2048, 256>>>();
    k_edge_pre<<<(EE * 4 + NN + 255) / 256, 256>>>(ei, ea, batch);
    k_scan1<<<NB_SCAN, 1024>>>();
    k_scan2<<<1, 128>>>();
    k_scan3<<<(NN + 255) / 256, 256>>>();
    k_place<<<(EE + 255) / 256, 256>>>(ei);

    // join
    cudaStreamWaitEvent(0, evJoin, 0);

    for (int l = 0; l < LL; l++) {
        k_gather4<<<(NN + 15) / 16, gblk>>>();
        k_fuse<<<148, blk>>>(l, m2W + l * 4096, m2b + l * 64, batch);
        k_fin<<<(GG * HH + 255) / 256, 256>>>();
        k_norm<<<(NN * 16 + 255) / 256, 256>>>(batch, nw + l * 64, nb + l * 64,
                                               (l == LL - 1) ? (float*)d_out : nullptr);
    }
}

// round 17
// speedup vs baseline: 1.4311x; 1.4311x over previous
#include <cuda_runtime.h>
#include <cuda_bf16.h>
#include <cstdint>

#define NN 100000
#define EE 1200000
#define HH 64
#define EDD 16
#define LL 3
#define GG 1000
#define NB_SCAN ((NN + 1023) / 1024)

// ---------------- device scratch ----------------
__device__ __align__(256) float g_h[NN * HH];
__device__ __align__(256) float g_S[NN * HH];
__device__ __align__(256) float g_tmp[NN * HH];
__device__ __align__(256) float g_aggea[NN * EDD];
__device__ __align__(256) float g_cnt[GG];
__device__ __align__(256) float g_sum[GG * HH];
__device__ __align__(256) float g_sumsq[GG * HH];
__device__ __align__(256) float g_mean[GG * HH];
__device__ __align__(256) float g_istd[GG * HH];
__device__ __align__(256) float g_A[LL * HH * HH];
__device__ __align__(256) float g_B[LL * HH * HH];
__device__ __align__(256) float g_C[LL * EDD * HH];
__device__ __align__(256) float g_c1[LL * HH];
__device__ __align__(256) float g_c2[LL * HH];
__device__ __align__(256) int g_degi[NN];
__device__ __align__(256) int g_rowoff[NN];
__device__ __align__(256) int g_cursor[NN];
__device__ __align__(256) int g_csrsrc[EE];
__device__ __align__(256) int g_bsum[NB_SCAN];

// ---------------- helpers ----------------
__device__ __forceinline__ uint64_t pack2(float lo, float hi) {
    uint64_t r; asm("mov.b64 %0, {%1,%2};" : "=l"(r) : "f"(lo), "f"(hi)); return r;
}
__device__ __forceinline__ void fma2(uint64_t& d, uint64_t a, uint64_t b) {
    asm("fma.rn.f32x2 %0, %1, %2, %0;" : "+l"(d) : "l"(a), "l"(b));
}
__device__ __forceinline__ float fold2(uint64_t a) {
    float lo, hi; asm("mov.b64 {%0,%1}, %2;" : "=f"(lo), "=f"(hi) : "l"(a)); return lo + hi;
}
__device__ __forceinline__ void red4(float* p, float4 v) {
    asm volatile("red.global.add.v4.f32 [%0], {%1,%2,%3,%4};"
                 :: "l"(p), "f"(v.x), "f"(v.y), "f"(v.z), "f"(v.w) : "memory");
}

// ---------------- once-per-call precompute ----------------
__global__ void k_zero_init() {
    const int o1 = NN * EDD, o2 = o1 + NN, o3 = o2 + GG, o4 = o3 + GG * HH, o5 = o4 + GG * HH;
    for (int i = blockIdx.x * blockDim.x + threadIdx.x; i < o5; i += gridDim.x * blockDim.x) {
        if (i < o1)      g_aggea[i] = 0.f;
        else if (i < o2) g_degi[i - o1] = 0;
        else if (i < o3) g_cnt[i - o2] = 0.f;
        else if (i < o4) g_sum[i - o3] = 0.f;
        else             g_sumsq[i - o4] = 0.f;
    }
}

// edge aggregation: 4 threads per edge (independent red4 per thread) + per-graph counts
__global__ void k_edge_pre(const int* __restrict__ ei, const float* __restrict__ ea,
                           const int* __restrict__ batch) {
    int t = blockIdx.x * 256 + threadIdx.x;
    if (t < EE * 4) {
        int e = t >> 2, q = t & 3;
        int d = __ldg(ei + EE + e);
        float4 v = __ldg((const float4*)(ea + (size_t)e * EDD) + q);
        red4(&g_aggea[(size_t)d * EDD + q * 4], v);
        if (q == 0) atomicAdd(&g_degi[d], 1);
    } else if (t < EE * 4 + NN) {
        int n = t - EE * 4;
        atomicAdd(&g_cnt[__ldg(batch + n)], 1.0f);
    }
}

__global__ void k_scan1() {
    __shared__ int warpsum[32];
    int tid = threadIdx.x, lane = tid & 31, w = tid >> 5;
    int i = blockIdx.x * 1024 + tid;
    int v = (i < NN) ? g_degi[i] : 0;
    int s = v;
#pragma unroll
    for (int o = 1; o < 32; o <<= 1) { int t = __shfl_up_sync(~0u, s, o); if (lane >= o) s += t; }
    if (lane == 31) warpsum[w] = s;
    __syncthreads();
    if (w == 0) {
        int ws = warpsum[lane];
#pragma unroll
        for (int o = 1; o < 32; o <<= 1) { int t = __shfl_up_sync(~0u, ws, o); if (lane >= o) ws += t; }
        warpsum[lane] = ws;
    }
    __syncthreads();
    int excl = s - v + (w ? warpsum[w - 1] : 0);
    if (i < NN) g_rowoff[i] = excl;
    if (tid == 1023) g_bsum[blockIdx.x] = excl + v;
}

__global__ void k_scan2() {
    __shared__ int warpsum[4];
    int tid = threadIdx.x, lane = tid & 31, w = tid >> 5;
    int v = (tid < NB_SCAN) ? g_bsum[tid] : 0;
    int s = v;
#pragma unroll
    for (int o = 1; o < 32; o <<= 1) { int t = __shfl_up_sync(~0u, s, o); if (lane >= o) s += t; }
    if (lane == 31) warpsum[w] = s;
    __syncthreads();
    int add = 0;
    for (int ww = 0; ww < w; ww++) add += warpsum[ww];
    if (tid < NB_SCAN) g_bsum[tid] = s - v + add;
}

__global__ void k_scan3() {
    int i = blockIdx.x * blockDim.x + threadIdx.x;
    if (i >= NN) return;
    int val = g_rowoff[i] + g_bsum[i >> 10];
    g_rowoff[i] = val;
    g_cursor[i] = val;
}

__global__ void k_place(const int* __restrict__ ei) {
    int e = blockIdx.x * 256 + threadIdx.x;
    if (e >= EE) return;
    int d = __ldg(ei + EE + e);
    int s = __ldg(ei + e);
    int pos = atomicAdd(&g_cursor[d], 1);
    g_csrsrc[pos] = s;
}

// fused weights for ALL layers in one launch
__global__ void k_pre(const float* __restrict__ nodeW, const float* __restrict__ edgeW,
                      const float* __restrict__ nodeb, const float* __restrict__ edgeb,
                      const float* __restrict__ m1W,   const float* __restrict__ m1b) {
    int j = threadIdx.x;
    int l = blockIdx.x / 81;
    int kb = blockIdx.x % 81;
    const float* nW = nodeW + l * 4096;
    const float* eW = edgeW + l * 1024;
    const float* nb = nodeb + l * 64;
    const float* eb = edgeb + l * 64;
    const float* w1 = m1W + l * 8192;
    const float* b1 = m1b + l * 64;
    if (kb < 64) {
        float a = 0.f, b = 0.f;
        for (int m = 0; m < 64; m++) {
            float wn = __ldg(nW + kb * 64 + m);
            a = fmaf(wn, __ldg(w1 + m * 64 + j), a);
            b = fmaf(wn, __ldg(w1 + (64 + m) * 64 + j), b);
        }
        g_A[l * 4096 + kb * 64 + j] = a;
        g_B[l * 4096 + kb * 64 + j] = b;
    } else if (kb < 80) {
        int k = kb - 64;
        float c = 0.f;
        for (int m = 0; m < 64; m++)
            c = fmaf(__ldg(eW + k * 64 + m), __ldg(w1 + (64 + m) * 64 + j), c);
        g_C[l * 1024 + k * 64 + j] = c;
    } else {
        float s1 = __ldg(b1 + j), s2 = 0.f;
        for (int m = 0; m < 64; m++) {
            s1 = fmaf(__ldg(nb + m), __ldg(w1 + m * 64 + j), s1);
            s2 = fmaf(__ldg(nb + m) + __ldg(eb + m), __ldg(w1 + (64 + m) * 64 + j), s2);
        }
        g_c1[l * 64 + j] = s1;
        g_c2[l * 64 + j] = s2;
    }
}

// ---------------- encoder: h = x @ enc_W + enc_b  (f32x2) ----------------
__global__ void __launch_bounds__(256, 2)
k_encoder(const float* __restrict__ X, const float* __restrict__ W, const float* __restrict__ Bv) {
    const int j = threadIdx.x, y = threadIdx.y;
    uint64_t w2[32];
#pragma unroll
    for (int p = 0; p < 32; p++)
        w2[p] = pack2(__ldg(W + (2 * p) * 64 + j), __ldg(W + (2 * p + 1) * 64 + j));
    const float bj = __ldg(Bv + j);
    __shared__ __align__(16) float xs[2][4][64];
    const int nT = NN / 4;
    int per = (nT + gridDim.x - 1) / gridDim.x;
    int t0 = blockIdx.x * per, t1 = min(nT, t0 + per);
    if (t0 >= t1) return;
    float pf = __ldg(X + (size_t)(t0 * 4 + y) * 64 + j);
    for (int tile = t0; tile < t1; ++tile) {
        int cur = tile & 1;
        xs[cur][y][j] = pf;
        __syncthreads();
        if (tile + 1 < t1) pf = __ldg(X + (size_t)((tile + 1) * 4 + y) * 64 + j);
        const uint64_t* xr = (const uint64_t*)xs[cur][y];
        uint64_t a0 = 0, a1 = 0, a2 = 0, a3 = 0;
#pragma unroll
        for (int p = 0; p < 32; p += 4) {
            fma2(a0, xr[p],     w2[p]);
            fma2(a1, xr[p + 1], w2[p + 1]);
            fma2(a2, xr[p + 2], w2[p + 2]);
            fma2(a3, xr[p + 3], w2[p + 3]);
        }
        g_h[(size_t)(tile * 4 + y) * 64 + j] = (fold2(a0) + fold2(a1)) + (fold2(a2) + fold2(a3)) + bj;
    }
}

// ---------------- gather (float4, unroll 8, occ 6 — champion config) ----------------
__global__ void __launch_bounds__(256, 6)
k_gather4() {
    const int j = threadIdx.x;
    const int y = threadIdx.y;
    int r = blockIdx.x * 16 + y;
    if (r >= NN) return;
    int p = __ldg(g_rowoff + r);
    const int p1 = (r + 1 < NN) ? __ldg(g_rowoff + r + 1) : EE;
    float4 a0 = make_float4(0.f, 0.f, 0.f, 0.f);
    float4 a1 = make_float4(0.f, 0.f, 0.f, 0.f);
    for (; p + 7 < p1; p += 8) {
        int s0 = __ldg(g_csrsrc + p);
        int s1 = __ldg(g_csrsrc + p + 1);
        int s2 = __ldg(g_csrsrc + p + 2);
        int s3 = __ldg(g_csrsrc + p + 3);
        int s4 = __ldg(g_csrsrc + p + 4);
        int s5 = __ldg(g_csrsrc + p + 5);
        int s6 = __ldg(g_csrsrc + p + 6);
        int s7 = __ldg(g_csrsrc + p + 7);
        float4 v0 = __ldg((const float4*)(g_h + (size_t)s0 * 64) + j);
        float4 v1 = __ldg((const float4*)(g_h + (size_t)s1 * 64) + j);
        float4 v2 = __ldg((const float4*)(g_h + (size_t)s2 * 64) + j);
        float4 v3 = __ldg((const float4*)(g_h + (size_t)s3 * 64) + j);
        float4 v4 = __ldg((const float4*)(g_h + (size_t)s4 * 64) + j);
        float4 v5 = __ldg((const float4*)(g_h + (size_t)s5 * 64) + j);
        float4 v6 = __ldg((const float4*)(g_h + (size_t)s6 * 64) + j);
        float4 v7 = __ldg((const float4*)(g_h + (size_t)s7 * 64) + j);
        a0.x += v0.x; a0.y += v0.y; a0.z += v0.z; a0.w += v0.w;
        a1.x += v1.x; a1.y += v1.y; a1.z += v1.z; a1.w += v1.w;
        a0.x += v2.x; a0.y += v2.y; a0.z += v2.z; a0.w += v2.w;
        a1.x += v3.x; a1.y += v3.y; a1.z += v3.z; a1.w += v3.w;
        a0.x += v4.x; a0.y += v4.y; a0.z += v4.z; a0.w += v4.w;
        a1.x += v5.x; a1.y += v5.y; a1.z += v5.z; a1.w += v5.w;
        a0.x += v6.x; a0.y += v6.y; a0.z += v6.z; a0.w += v6.w;
        a1.x += v7.x; a1.y += v7.y; a1.z += v7.z; a1.w += v7.w;
    }
    for (; p < p1; p++) {
        int s = __ldg(g_csrsrc + p);
        float4 v = __ldg((const float4*)(g_h + (size_t)s * 64) + j);
        a0.x += v.x; a0.y += v.y; a0.z += v.z; a0.w += v.w;
    }
    float4 o;
    o.x = a0.x + a1.x; o.y = a0.y + a1.y; o.z = a0.z + a1.z; o.w = a0.w + a1.w;
    ((float4*)(g_S + (size_t)r * 64))[j] = o;
}

// ---------------- merged fuse (champion: 8-row tiles, scalar Phase A w/ LDS.128, FFMA2 Phase B) ------
__global__ void __launch_bounds__(256, 1)
k_fuse(int l, const float* __restrict__ W2, const float* __restrict__ b2v,
       const int* __restrict__ batch) {
    const int j = threadIdx.x, y = threadIdx.y;
    const float* gA = g_A + l * 4096;
    const float* gB = g_B + l * 4096;
    const float* gC = g_C + l * 1024;
    float wa[64], wb[64];
#pragma unroll
    for (int k = 0; k < 64; k++) { wa[k] = gA[k * 64 + j]; wb[k] = gB[k * 64 + j]; }
    uint64_t w2[32];
#pragma unroll
    for (int p = 0; p < 32; p++)
        w2[p] = pack2(__ldg(W2 + (2 * p) * 64 + j), __ldg(W2 + (2 * p + 1) * 64 + j));
    const float b1 = g_c1[l * 64 + j], b2 = g_c2[l * 64 + j];
    const float bj2 = __ldg(b2v + j);

    __shared__ __align__(16) float hs[2][8][64], Ss[2][8][64], eas[2][8][16];
    __shared__ float degs[2][8];
    __shared__ float Csh[16][64];
    __shared__ __align__(16) float Tsh[8][64];
    {
        int tid = y * 64 + j;
        for (int i = tid; i < 16 * 64; i += 256) Csh[i >> 6][i & 63] = gC[i];
    }
    const int nT = NN / 8;
    int per = (nT + gridDim.x - 1) / gridDim.x;
    int t0 = blockIdx.x * per, t1 = min(nT, t0 + per);
    if (t0 >= t1) return;

    float csA = 0.f, cqA = 0.f, csB = 0.f, cqB = 0.f;
    int cgA = -1, cgB = -1;

    float ph0, ph1, pS0, pS1, pea0 = 0.f, pea1 = 0.f, pd0 = 0.f, pd1 = 0.f;
    {
        size_t r0 = (size_t)(t0 * 8 + y), r1 = r0 + 4;
        ph0 = __ldg(g_h + r0 * 64 + j);  ph1 = __ldg(g_h + r1 * 64 + j);
        pS0 = __ldg(g_S + r0 * 64 + j);  pS1 = __ldg(g_S + r1 * 64 + j);
        if (j < 16) { pea0 = __ldg(g_aggea + r0 * 16 + j); pea1 = __ldg(g_aggea + r1 * 16 + j); }
        if (j == 0) { pd0 = (float)__ldg(g_degi + (int)r0); pd1 = (float)__ldg(g_degi + (int)r1); }
    }
    for (int tile = t0; tile < t1; ++tile) {
        int cur = tile & 1;
        hs[cur][y][j] = ph0;  hs[cur][y + 4][j] = ph1;
        Ss[cur][y][j] = pS0;  Ss[cur][y + 4][j] = pS1;
        if (j < 16) { eas[cur][y][j] = pea0; eas[cur][y + 4][j] = pea1; }
        if (j == 0) { degs[cur][y] = pd0; degs[cur][y + 4] = pd1; }
        __syncthreads();
        if (tile + 1 < t1) {
            size_t r0 = (size_t)((tile + 1) * 8 + y), r1 = r0 + 4;
            ph0 = __ldg(g_h + r0 * 64 + j);  ph1 = __ldg(g_h + r1 * 64 + j);
            pS0 = __ldg(g_S + r0 * 64 + j);  pS1 = __ldg(g_S + r1 * 64 + j);
            if (j < 16) { pea0 = __ldg(g_aggea + r0 * 16 + j); pea1 = __ldg(g_aggea + r1 * 16 + j); }
            if (j == 0) { pd0 = (float)__ldg(g_degi + (int)r0); pd1 = (float)__ldg(g_degi + (int)r1); }
        }
        // ---- Phase A: scalar FMA, operands via float4 LDS.128 ----
        {
            const float4* h4A = (const float4*)hs[cur][y];
            const float4* S4A = (const float4*)Ss[cur][y];
            const float4* h4B = (const float4*)hs[cur][y + 4];
            const float4* S4B = (const float4*)Ss[cur][y + 4];
            float u0 = 0.f, u1 = 0.f, u2 = 0.f, u3 = 0.f;
            float v0 = 0.f, v1 = 0.f, v2 = 0.f, v3 = 0.f;
            float x0 = 0.f, x1 = 0.f, x2 = 0.f, x3 = 0.f;
            float z0 = 0.f, z1 = 0.f, z2 = 0.f, z3 = 0.f;
#pragma unroll
            for (int q = 0; q < 16; q++) {
                float4 ha = h4A[q];
                float4 sa = S4A[q];
                float4 hb = h4B[q];
                float4 sb = S4B[q];
                u0 = fmaf(ha.x, wa[4 * q],     u0);
                u1 = fmaf(ha.y, wa[4 * q + 1], u1);
                u2 = fmaf(ha.z, wa[4 * q + 2], u2);
                u3 = fmaf(ha.w, wa[4 * q + 3], u3);
                v0 = fmaf(sa.x, wb[4 * q],     v0);
                v1 = fmaf(sa.y, wb[4 * q + 1], v1);
                v2 = fmaf(sa.z, wb[4 * q + 2], v2);
                v3 = fmaf(sa.w, wb[4 * q + 3], v3);
                x0 = fmaf(hb.x, wa[4 * q],     x0);
                x1 = fmaf(hb.y, wa[4 * q + 1], x1);
                x2 = fmaf(hb.z, wa[4 * q + 2], x2);
                x3 = fmaf(hb.w, wa[4 * q + 3], x3);
                z0 = fmaf(sb.x, wb[4 * q],     z0);
                z1 = fmaf(sb.y, wb[4 * q + 1], z1);
                z2 = fmaf(sb.z, wb[4 * q + 2], z2);
                z3 = fmaf(sb.w, wb[4 * q + 3], z3);
            }
            const float4* e4A = (const float4*)eas[cur][y];
            const float4* e4B = (const float4*)eas[cur][y + 4];
#pragma unroll
            for (int q = 0; q < 4; q++) {
                float4 ca = e4A[q];
                float4 cb = e4B[q];
                u0 = fmaf(ca.x, Csh[4 * q][j],     u0);
                u1 = fmaf(ca.y, Csh[4 * q + 1][j], u1);
                u2 = fmaf(ca.z, Csh[4 * q + 2][j], u2);
                u3 = fmaf(ca.w, Csh[4 * q + 3][j], u3);
                x0 = fmaf(cb.x, Csh[4 * q][j],     x0);
                x1 = fmaf(cb.y, Csh[4 * q + 1][j], x1);
                x2 = fmaf(cb.z, Csh[4 * q + 2][j], x2);
                x3 = fmaf(cb.w, Csh[4 * q + 3][j], x3);
            }
            float valA = ((u0 + u1) + (u2 + u3)) + ((v0 + v1) + (v2 + v3)) + b1 + degs[cur][y] * b2;
            float valB = ((x0 + x1) + (x2 + x3)) + ((z0 + z1) + (z2 + z3)) + b1 + degs[cur][y + 4] * b2;
            Tsh[y][j]     = fmaxf(valA, 0.f);
            Tsh[y + 4][j] = fmaxf(valB, 0.f);
        }
        __syncthreads();
        // ---- Phase B: tmp = Tsh @ W2 + b2 (FFMA2, LDS.128 pair loads), plus stats ----
        {
            const ulonglong2* trA = (const ulonglong2*)Tsh[y];
            const ulonglong2* trB = (const ulonglong2*)Tsh[y + 4];
            uint64_t a0 = 0, a1 = 0, a2 = 0, a3 = 0;
            uint64_t c0 = 0, c1 = 0, c2 = 0, c3 = 0;
#pragma unroll
            for (int q = 0; q < 16; q += 2) {
                ulonglong2 ta = trA[q];
                ulonglong2 tb = trB[q];
                ulonglong2 ta2 = trA[q + 1];
                ulonglong2 tb2 = trB[q + 1];
                fma2(a0, ta.x,  w2[2 * q]);
                fma2(a1, ta.y,  w2[2 * q + 1]);
                fma2(a2, ta2.x, w2[2 * q + 2]);
                fma2(a3, ta2.y, w2[2 * q + 3]);
                fma2(c0, tb.x,  w2[2 * q]);
                fma2(c1, tb.y,  w2[2 * q + 1]);
                fma2(c2, tb2.x, w2[2 * q + 2]);
                fma2(c3, tb2.y, w2[2 * q + 3]);
            }
            int rA = tile * 8 + y, rB = rA + 4;
            float vA = (fold2(a0) + fold2(a1)) + (fold2(a2) + fold2(a3)) + bj2;
            float vB = (fold2(c0) + fold2(c1)) + (fold2(c2) + fold2(c3)) + bj2;
            g_tmp[(size_t)rA * 64 + j] = vA;
            g_tmp[(size_t)rB * 64 + j] = vB;
            int gA2 = __ldg(batch + rA);
            if (gA2 != cgA) {
                if (cgA >= 0) { atomicAdd(&g_sum[cgA * 64 + j], csA); atomicAdd(&g_sumsq[cgA * 64 + j], cqA); }
                cgA = gA2; csA = 0.f; cqA = 0.f;
            }
            csA += vA; cqA += vA * vA;
            int gB2 = __ldg(batch + rB);
            if (gB2 != cgB) {
                if (cgB >= 0) { atomicAdd(&g_sum[cgB * 64 + j], csB); atomicAdd(&g_sumsq[cgB * 64 + j], cqB); }
                cgB = gB2; csB = 0.f; cqB = 0.f;
            }
            csB += vB; cqB += vB * vB;
        }
    }
    if (cgA >= 0) { atomicAdd(&g_sum[cgA * 64 + j], csA); atomicAdd(&g_sumsq[cgA * 64 + j], cqA); }
    if (cgB >= 0) { atomicAdd(&g_sum[cgB * 64 + j], csB); atomicAdd(&g_sumsq[cgB * 64 + j], cqB); }
}

// compute mean/istd, then zero stats for next layer
__global__ void k_fin() {
    int i = blockIdx.x * blockDim.x + threadIdx.x;
    if (i >= GG * HH) return;
    int g = i >> 6;
    float c = fmaxf(g_cnt[g], 1.0f);
    float m = g_sum[i] / c;
    float v = g_sumsq[i] / c - m * m;
    g_mean[i] = m;
    g_istd[i] = rsqrtf(v + 1e-5f);
    g_sum[i] = 0.f;
    g_sumsq[i] = 0.f;
}

__global__ void k_norm(const int* __restrict__ batch, const float* __restrict__ nw,
                       const float* __restrict__ nb, float* __restrict__ out) {
    int i = blockIdx.x * blockDim.x + threadIdx.x;
    if (i >= NN * 16) return;
    int n = i >> 4, q = i & 15;
    int g = __ldg(batch + n);
    float4 t  = *((const float4*)g_tmp + i);
    float4 m  = *((const float4*)g_mean + g * 16 + q);
    float4 is = *((const float4*)g_istd + g * 16 + q);
    float4 w  = __ldg((const float4*)nw + q);
    float4 b  = __ldg((const float4*)nb + q);
    float4 r  = *((const float4*)g_h + i);
    float4 o;
    o.x = fmaxf(fmaf(w.x, (t.x - m.x) * is.x, b.x), 0.f) + r.x;
    o.y = fmaxf(fmaf(w.y, (t.y - m.y) * is.y, b.y), 0.f) + r.y;
    o.z = fmaxf(fmaf(w.z, (t.z - m.z) * is.z, b.z), 0.f) + r.z;
    o.w = fmaxf(fmaf(w.w, (t.w - m.w) * is.w, b.w), 0.f) + r.w;
    float4* dst = out ? (float4*)out : (float4*)g_h;
    dst[i] = o;
}

// ---------------- launch ----------------
extern "C" void kernel_launch(void* const* d_in, const int* in_sizes, int n_in,
                              void* d_out, int out_size) {
    const float* x     = (const float*)d_in[0];
    const int*   ei    = (const int*)  d_in[1];
    const float* ea    = (const float*)d_in[2];
    const int*   batch = (const int*)  d_in[3];
    const float* encW  = (const float*)d_in[4];
    const float* encb  = (const float*)d_in[5];
    const float* nodeW = (const float*)d_in[6];
    const float* nodeb = (const float*)d_in[7];
    const float* edgeW = (const float*)d_in[8];
    const float* edgeb = (const float*)d_in[9];
    const float* m1W   = (const float*)d_in[10];
    const float* m1b   = (const float*)d_in[11];
    const float* m2W   = (const float*)d_in[12];
    const float* m2b   = (const float*)d_in[13];
    const float* nw    = (const float*)d_in[14];
    const float* nb    = (const float*)d_in[15];

    dim3 blk(64, 4);
    dim3 gblk(16, 16);

    static cudaStream_t s2 = nullptr;
    static cudaEvent_t evFork = nullptr, evJoin = nullptr;
    if (!s2) {
        cudaStreamCreateWithFlags(&s2, cudaStreamNonBlocking);
        cudaEventCreateWithFlags(&evFork, cudaEventDisableTiming);
        cudaEventCreateWithFlags(&evJoin, cudaEventDisableTiming);
    }

    // fork: side stream runs k_pre + encoder concurrently with the CSR build
    cudaEventRecord(evFork, 0);
    cudaStreamWaitEvent(s2, evFork, 0);
    k_pre<<<LL * 81, 64, 0, s2>>>(nodeW, edgeW, nodeb, edgeb, m1W, m1b);
    k_encoder<<<296, blk, 0, s2>>>(x, encW, encb);
    cudaEventRecord(evJoin, s2);

    // main stream: CSR build chain
    k_zero_init<<<2048, 256>>>();
    k_edge_pre<<<(EE * 4 + NN + 255) / 256, 256>>>(ei, ea, batch);
    k_scan1<<<NB_SCAN, 1024>>>();
    k_scan2<<<1, 128>>>();
    k_scan3<<<(NN + 255) / 256, 256>>>();
    k_place<<<(EE + 255) / 256, 256>>>(ei);

    // join
    cudaStreamWaitEvent(0, evJoin, 0);

    for (int l = 0; l < LL; l++) {
        k_gather4<<<(NN + 15) / 16, gblk>>>();
        k_fuse<<<148, blk>>>(l, m2W + l * 4096, m2b + l * 64, batch);
        k_fin<<<(GG * HH + 255) / 256, 256>>>();
        k_norm<<<(NN * 16 + 255) / 256, 256>>>(batch, nw + l * 64, nb + l * 64,
                                               (l == LL - 1) ? (float*)d_out : nullptr);
    }
}